// round 16
// baseline (speedup 1.0000x reference)
#include <cuda_runtime.h>
#include <cuda_bf16.h>
#include <math.h>
#include <stdint.h>

#define NB 32
#define NN 512
#define ND 256
#define NH 8
#define HDIM 32
#define BND (NB * NN * ND)

// ---------------- scratch (device globals; no allocation allowed) ----------
__device__ float g_A[NN * NN];          // integer edge counts (+I)
__device__ int   g_deg[NN];
__device__ float g_dinv[NN];
__device__ int   g_odd;                 // 0 -> 1 if any odd word != 0 (int32 data)
__device__ uint32_t g_maskw[NN * 16];

__device__ __nv_bfloat16 g_INh[3][BND], g_INl[3][BND];   // dinv-scaled inputs
__device__ __nv_bfloat16 g_Wh[4][ND * ND], g_Wl[4][ND * ND];
__device__ __nv_bfloat16 g_Ah[NN * NN];                  // integer Adj+I (exact bf16)
__device__ __nv_bfloat16 g_XWh[3][BND], g_XWl[3][BND];   // Y = (Dinv X) W
__device__ __nv_bfloat16 g_QVh[3][BND], g_QVl[3][BND];
__device__ __nv_bfloat16 g_ATh[BND], g_ATl[BND];

// ================= helpers =================================================
__device__ __forceinline__ uint32_t smem_u32(const void* p) {
    uint32_t a;
    asm("{ .reg .u64 t; cvta.to.shared.u64 t, %1; cvt.u32.u64 %0, t; }"
        : "=r"(a) : "l"(p));
    return a;
}
__device__ __forceinline__ void cp16(uint32_t s, const void* g) {
    asm volatile("cp.async.cg.shared.global [%0], [%1], 16;" :: "r"(s), "l"(g));
}
#define CP_COMMIT() asm volatile("cp.async.commit_group;" ::: "memory")
#define CP_WAIT1()  asm volatile("cp.async.wait_group 1;" ::: "memory")
__device__ __forceinline__ void ldsm_x4(uint32_t r[4], uint32_t addr) {
    asm volatile("ldmatrix.sync.aligned.m8n8.x4.shared.b16 {%0,%1,%2,%3}, [%4];"
                 : "=r"(r[0]), "=r"(r[1]), "=r"(r[2]), "=r"(r[3]) : "r"(addr));
}
__device__ __forceinline__ void ldsm_x4_t(uint32_t r[4], uint32_t addr) {
    asm volatile("ldmatrix.sync.aligned.m8n8.x4.trans.shared.b16 {%0,%1,%2,%3}, [%4];"
                 : "=r"(r[0]), "=r"(r[1]), "=r"(r[2]), "=r"(r[3]) : "r"(addr));
}
__device__ __forceinline__ void mma16816(float c[4], const uint32_t a[4],
                                         uint32_t b0, uint32_t b1) {
    asm volatile(
        "mma.sync.aligned.m16n8k16.row.col.f32.bf16.bf16.f32 "
        "{%0,%1,%2,%3}, {%4,%5,%6,%7}, {%8,%9}, {%0,%1,%2,%3};"
        : "+f"(c[0]), "+f"(c[1]), "+f"(c[2]), "+f"(c[3])
        : "r"(a[0]), "r"(a[1]), "r"(a[2]), "r"(a[3]), "r"(b0), "r"(b1));
}
__device__ __forceinline__ uint32_t pack2bf(float lo, float hi) {
    uint32_t r;
    asm("cvt.rn.bf16x2.f32 %0, %1, %2;" : "=r"(r) : "f"(hi), "f"(lo));
    return r;
}
__device__ __forceinline__ float bf_lo(uint32_t w) { return __uint_as_float(w << 16); }
__device__ __forceinline__ float bf_hi(uint32_t w) { return __uint_as_float(w & 0xFFFF0000u); }

__device__ __forceinline__ float exp2_fast(float x) {
    float z = x + 12582912.0f;
    float f = x - (z - 12582912.0f);
    int eb = __float_as_int(z) << 23;
    float p = fmaf(f, 0.00961813f, 0.05550411f);
    p = fmaf(f, p, 0.24022651f);
    p = fmaf(f, p, 0.69314718f);
    p = fmaf(f, p, 1.0f);
    return __int_as_float(__float_as_int(p) + eb);
}

// ---------------- preprocessing --------------------------------------------
__global__ void k_initmask(const int* __restrict__ mask, const int* __restrict__ ew, int E) {
    int i = blockIdx.x * blockDim.x + threadIdx.x;
    if (i < NN * NN) g_A[i] = 0.0f;
    if (i < NN) g_deg[i] = 1;
    if (i < E && ew[2 * i + 1] != 0) g_odd = 1;
    int wid = i >> 5, lane = i & 31;
    if (wid < NN * 16) {
        int row = wid >> 4, word = wid & 15;
        int v = mask[row * NN + word * 32 + lane];
        unsigned bal = __ballot_sync(0xffffffffu, v != 0);
        if (lane == 0) g_maskw[wid] = bal;
    }
}
__device__ __forceinline__ int edge_src(const int* w, int E, int i) {
    return g_odd ? w[i] : w[2 * i];
}
__device__ __forceinline__ int edge_dst(const int* w, int E, int i) {
    return g_odd ? w[E + i] : w[2 * E + 2 * i];
}
__global__ void k_deg(const int* __restrict__ w, int E) {
    int i = blockIdx.x * blockDim.x + threadIdx.x;
    if (i < E) {
        int d = edge_dst(w, E, i);
        if (d >= 0 && d < NN) atomicAdd(&g_deg[d], 1);
    }
}
__global__ void k_dinv() {
    int i = blockIdx.x * blockDim.x + threadIdx.x;
    if (i < NN) g_dinv[i] = rsqrtf((float)g_deg[i]);
}
__global__ void k_buildA(const int* __restrict__ w, int E) {
    int i = blockIdx.x * blockDim.x + threadIdx.x;
    if (i < E) {
        int s = edge_src(w, E, i);
        int d = edge_dst(w, E, i);
        if (s >= 0 && s < NN && d >= 0 && d < NN)
            atomicAdd(&g_A[d * NN + s], 1.0f);
    } else if (i < E + NN) {
        int n = i - E;
        atomicAdd(&g_A[n * NN + n], 1.0f);
    }
}
__global__ void k_convertA() {
    int i = blockIdx.x * blockDim.x + threadIdx.x;
    if (i < NN * NN / 2) {
        float2 v = ((const float2*)g_A)[i];
        ((uint32_t*)g_Ah)[i] = pack2bf(v.x, v.y);
    }
}
__global__ void k_split3(const float* __restrict__ s0, const float* __restrict__ s1,
                         const float* __restrict__ s2,
                         __nv_bfloat16* __restrict__ hi, __nv_bfloat16* __restrict__ lo,
                         int n2) {
    int i = blockIdx.x * blockDim.x + threadIdx.x;
    int t = blockIdx.y;
    const float* src = (t == 0) ? s0 : (t == 1 ? s1 : s2);
    long long off = (long long)t * n2;
    if (i < n2) {
        float sc = g_dinv[((2 * i) / ND) % NN];
        float2 v = ((const float2*)src)[i];
        v.x *= sc; v.y *= sc;
        uint32_t hw = pack2bf(v.x, v.y);
        uint32_t lw = pack2bf(v.x - bf_lo(hw), v.y - bf_hi(hw));
        ((uint32_t*)hi)[off + i] = hw;
        ((uint32_t*)lo)[off + i] = lw;
    }
}
__global__ void k_split4(const float* __restrict__ s0, const float* __restrict__ s1,
                         const float* __restrict__ s2, const float* __restrict__ s3,
                         __nv_bfloat16* __restrict__ hi, __nv_bfloat16* __restrict__ lo,
                         int n2) {
    int i = blockIdx.x * blockDim.x + threadIdx.x;
    int t = blockIdx.y;
    const float* src = (t == 0) ? s0 : (t == 1 ? s1 : (t == 2 ? s2 : s3));
    long long off = (long long)t * n2;
    if (i < n2) {
        float2 v = ((const float2*)src)[i];
        uint32_t hw = pack2bf(v.x, v.y);
        uint32_t lw = pack2bf(v.x - bf_lo(hw), v.y - bf_hi(hw));
        ((uint32_t*)hi)[off + i] = hw;
        ((uint32_t*)lo)[off + i] = lw;
    }
}

// ================= GEMM common ==============================================
#define KC 32
#define SRA 40
#define GA_TILE (128 * SRA)

struct BiasPtrs { const float *b0, *b1, *b2; };

// ---- 3-pass GEMM (A hi/lo x B hi/lo), templated N-tile = 32*NJ ------------
template <int NJ>
__global__ __launch_bounds__(256, 2) void gemm3(
    const __nv_bfloat16* __restrict__ Ah, const __nv_bfloat16* __restrict__ Al,
    long long sAi, long long sAb,
    const __nv_bfloat16* __restrict__ Bh, const __nv_bfloat16* __restrict__ Bl,
    long long sBi, long long sBb,
    BiasPtrs bp,
    float* __restrict__ Cf,
    __nv_bfloat16* __restrict__ Ch, __nv_bfloat16* __restrict__ Cl,
    long long sCi, long long sCb,
    int Nn, int K, int zbits)
{
    constexpr int NT = 32 * NJ;
    constexpr int SRBt = NT + 8;
    constexpr int OCTS = NT / 8;
    constexpr int GBt = KC * SRBt;
    constexpr int STAGE = 2 * GA_TILE + 2 * GBt;

    extern __shared__ char dsm[];
    __nv_bfloat16* sm = (__nv_bfloat16*)dsm;

    const int z = blockIdx.z;
    const int zi = z >> zbits;
    const int zb = z & ((1 << zbits) - 1);
    const long long aoff = zi * sAi + zb * sAb;
    const long long boff = zi * sBi + zb * sBb;
    const long long coff = zi * sCi + zb * sCb;
    const float* bias = (zi == 0) ? bp.b0 : (zi == 1 ? bp.b1 : bp.b2);
    Ah += aoff; Al += aoff; Bh += boff; Bl += boff;

    const int m0 = blockIdx.y * 128, n0 = blockIdx.x * NT;
    const int tid = threadIdx.x, wid = tid >> 5, lane = tid & 31;
    const int wm = wid & 3, wn = wid >> 2;

    auto stA = [&](int st, int p) { return sm + st * STAGE + p * GA_TILE; };
    auto stB = [&](int st, int p) { return sm + st * STAGE + 2 * GA_TILE + p * GBt; };

    auto issue = [&](int st, int kc) {
        #pragma unroll
        for (int p = 0; p < 2; p++) {
            const __nv_bfloat16* ga = p ? Al : Ah;
            uint32_t abase = smem_u32(stA(st, p));
            #pragma unroll
            for (int j = 0; j < 2; j++) {
                int lin = tid + j * 256;
                int row = lin >> 2, oct = lin & 3;
                cp16(abase + (row * SRA + oct * 8) * 2,
                     ga + (long long)(m0 + row) * K + kc + oct * 8);
            }
            const __nv_bfloat16* gb = p ? Bl : Bh;
            uint32_t bbase = smem_u32(stB(st, p));
            #pragma unroll
            for (int j = 0; j < (32 * OCTS) / 256; j++) {
                int lin = tid + j * 256;
                int k = lin / OCTS, oct = lin % OCTS;
                cp16(bbase + (k * SRBt + oct * 8) * 2,
                     gb + (long long)(kc + k) * Nn + n0 + oct * 8);
            }
        }
    };

    float acc[2][2 * NJ][4];
    #pragma unroll
    for (int i = 0; i < 2; i++)
        #pragma unroll
        for (int j = 0; j < 2 * NJ; j++)
            #pragma unroll
            for (int l = 0; l < 4; l++) acc[i][j][l] = 0.0f;

    const int nk = K / KC;
    issue(0, 0); CP_COMMIT();
    issue(1, KC); CP_COMMIT();

    for (int it = 0; it < nk; it++) {
        CP_WAIT1();
        __syncthreads();
        if (it + 2 < nk) issue((it + 2) % 3, (it + 2) * KC);
        CP_COMMIT();
        const int st = it % 3;
        const __nv_bfloat16* a0 = stA(st, 0);
        const __nv_bfloat16* a1 = stA(st, 1);
        const __nv_bfloat16* b0p = stB(st, 0);
        const __nv_bfloat16* b1p = stB(st, 1);

        #pragma unroll
        for (int ks = 0; ks < 2; ks++) {
            uint32_t ah[2][4], al4[2][4];
            #pragma unroll
            for (int mi = 0; mi < 2; mi++) {
                ldsm_x4(ah[mi], smem_u32(a0 + (wm * 32 + mi * 16 + (lane & 15)) * SRA
                                            + ks * 16 + (lane >> 4) * 8));
                ldsm_x4(al4[mi], smem_u32(a1 + (wm * 32 + mi * 16 + (lane & 15)) * SRA
                                             + ks * 16 + (lane >> 4) * 8));
            }
            #pragma unroll
            for (int nj = 0; nj < NJ; nj++) {
                uint32_t bh4[4], bl4[4];
                ldsm_x4_t(bh4, smem_u32(b0p + (ks * 16 + (lane & 15)) * SRBt
                                            + wn * (16 * NJ) + nj * 16 + (lane >> 4) * 8));
                ldsm_x4_t(bl4, smem_u32(b1p + (ks * 16 + (lane & 15)) * SRBt
                                            + wn * (16 * NJ) + nj * 16 + (lane >> 4) * 8));
                mma16816(acc[0][nj * 2 + 0], ah[0], bh4[0], bh4[1]);
                mma16816(acc[0][nj * 2 + 1], ah[0], bh4[2], bh4[3]);
                mma16816(acc[1][nj * 2 + 0], ah[1], bh4[0], bh4[1]);
                mma16816(acc[1][nj * 2 + 1], ah[1], bh4[2], bh4[3]);
                mma16816(acc[0][nj * 2 + 0], ah[0], bl4[0], bl4[1]);
                mma16816(acc[0][nj * 2 + 1], ah[0], bl4[2], bl4[3]);
                mma16816(acc[1][nj * 2 + 0], ah[1], bl4[0], bl4[1]);
                mma16816(acc[1][nj * 2 + 1], ah[1], bl4[2], bl4[3]);
                mma16816(acc[0][nj * 2 + 0], al4[0], bh4[0], bh4[1]);
                mma16816(acc[0][nj * 2 + 1], al4[0], bh4[2], bh4[3]);
                mma16816(acc[1][nj * 2 + 0], al4[1], bh4[0], bh4[1]);
                mma16816(acc[1][nj * 2 + 1], al4[1], bh4[2], bh4[3]);
            }
        }
    }

    const int r0 = lane >> 2;
    const int cp = (lane & 3) * 2;
    #pragma unroll
    for (int mi = 0; mi < 2; mi++) {
        int rbase = m0 + wm * 32 + mi * 16;
        #pragma unroll
        for (int nt = 0; nt < 2 * NJ; nt++) {
            int col = n0 + wn * (16 * NJ) + nt * 8 + cp;
            float bx = bias ? bias[col] : 0.0f;
            float by = bias ? bias[col + 1] : 0.0f;
            float v00 = acc[mi][nt][0] + bx, v01 = acc[mi][nt][1] + by;
            float v10 = acc[mi][nt][2] + bx, v11 = acc[mi][nt][3] + by;
            long long i0 = coff + (long long)(rbase + r0) * Nn + col;
            long long i1 = coff + (long long)(rbase + r0 + 8) * Nn + col;
            if (Cf) {
                *(float2*)&Cf[i0] = make_float2(v00, v01);
                *(float2*)&Cf[i1] = make_float2(v10, v11);
            }
            if (Ch) {
                uint32_t h0 = pack2bf(v00, v01);
                uint32_t h1 = pack2bf(v10, v11);
                *(uint32_t*)&Ch[i0] = h0;
                *(uint32_t*)&Ch[i1] = h1;
                *(uint32_t*)&Cl[i0] = pack2bf(v00 - bf_lo(h0), v01 - bf_hi(h0));
                *(uint32_t*)&Cl[i1] = pack2bf(v10 - bf_lo(h1), v11 - bf_hi(h1));
            }
        }
    }
}

// ---- 2-pass GEMM (exact A single-plane x B hi/lo), rowscale epilogue ------
#define SRB 136
#define GB_TILE (KC * SRB)
#define G2_STAGE (GA_TILE + 2 * GB_TILE)
#define G2_SMEM (3 * G2_STAGE * 2)

__global__ __launch_bounds__(256, 2) void gemm2(
    const __nv_bfloat16* __restrict__ Am,
    const __nv_bfloat16* __restrict__ Bh, const __nv_bfloat16* __restrict__ Bl,
    long long sBi, long long sBb,
    BiasPtrs bp, const float* __restrict__ rsc,
    __nv_bfloat16* __restrict__ Ch, __nv_bfloat16* __restrict__ Cl,
    long long sCi, long long sCb,
    int Nn, int K, int zbits)
{
    extern __shared__ char dsm[];
    __nv_bfloat16* sm = (__nv_bfloat16*)dsm;

    const int z = blockIdx.z;
    const int zi = z >> zbits;
    const int zb = z & ((1 << zbits) - 1);
    const long long boff = zi * sBi + zb * sBb;
    const long long coff = zi * sCi + zb * sCb;
    const float* bias = (zi == 0) ? bp.b0 : (zi == 1 ? bp.b1 : bp.b2);
    Bh += boff; Bl += boff;

    const int m0 = blockIdx.y * 128, n0 = blockIdx.x * 128;
    const int tid = threadIdx.x, wid = tid >> 5, lane = tid & 31;
    const int wm = wid & 3, wn = wid >> 2;

    auto stA = [&](int st) { return sm + st * G2_STAGE; };
    auto stB = [&](int st, int p) { return sm + st * G2_STAGE + GA_TILE + p * GB_TILE; };

    auto issue = [&](int st, int kc) {
        uint32_t abase = smem_u32(stA(st));
        #pragma unroll
        for (int j = 0; j < 2; j++) {
            int lin = tid + j * 256;
            int row = lin >> 2, oct = lin & 3;
            cp16(abase + (row * SRA + oct * 8) * 2,
                 Am + (long long)(m0 + row) * K + kc + oct * 8);
        }
        #pragma unroll
        for (int p = 0; p < 2; p++) {
            const __nv_bfloat16* gb = p ? Bl : Bh;
            uint32_t bbase = smem_u32(stB(st, p));
            #pragma unroll
            for (int j = 0; j < 2; j++) {
                int lin = tid + j * 256;
                int k = lin >> 4, oct = lin & 15;
                cp16(bbase + (k * SRB + oct * 8) * 2,
                     gb + (long long)(kc + k) * Nn + n0 + oct * 8);
            }
        }
    };

    float acc[2][8][4];
    #pragma unroll
    for (int i = 0; i < 2; i++)
        #pragma unroll
        for (int j = 0; j < 8; j++)
            #pragma unroll
            for (int l = 0; l < 4; l++) acc[i][j][l] = 0.0f;

    const int nk = K / KC;
    issue(0, 0); CP_COMMIT();
    issue(1, KC); CP_COMMIT();

    for (int it = 0; it < nk; it++) {
        CP_WAIT1();
        __syncthreads();
        if (it + 2 < nk) issue((it + 2) % 3, (it + 2) * KC);
        CP_COMMIT();
        const int st = it % 3;
        const __nv_bfloat16* a0 = stA(st);
        const __nv_bfloat16* b0p = stB(st, 0);
        const __nv_bfloat16* b1p = stB(st, 1);

        #pragma unroll
        for (int ks = 0; ks < 2; ks++) {
            uint32_t am[2][4];
            #pragma unroll
            for (int mi = 0; mi < 2; mi++)
                ldsm_x4(am[mi], smem_u32(a0 + (wm * 32 + mi * 16 + (lane & 15)) * SRA
                                            + ks * 16 + (lane >> 4) * 8));
            #pragma unroll
            for (int nj = 0; nj < 4; nj++) {
                uint32_t bh4[4], bl4[4];
                ldsm_x4_t(bh4, smem_u32(b0p + (ks * 16 + (lane & 15)) * SRB
                                            + wn * 64 + nj * 16 + (lane >> 4) * 8));
                ldsm_x4_t(bl4, smem_u32(b1p + (ks * 16 + (lane & 15)) * SRB
                                            + wn * 64 + nj * 16 + (lane >> 4) * 8));
                mma16816(acc[0][nj * 2 + 0], am[0], bh4[0], bh4[1]);
                mma16816(acc[0][nj * 2 + 1], am[0], bh4[2], bh4[3]);
                mma16816(acc[1][nj * 2 + 0], am[1], bh4[0], bh4[1]);
                mma16816(acc[1][nj * 2 + 1], am[1], bh4[2], bh4[3]);
                mma16816(acc[0][nj * 2 + 0], am[0], bl4[0], bl4[1]);
                mma16816(acc[0][nj * 2 + 1], am[0], bl4[2], bl4[3]);
                mma16816(acc[1][nj * 2 + 0], am[1], bl4[0], bl4[1]);
                mma16816(acc[1][nj * 2 + 1], am[1], bl4[2], bl4[3]);
            }
        }
    }

    const int r0 = lane >> 2;
    const int cp = (lane & 3) * 2;
    #pragma unroll
    for (int mi = 0; mi < 2; mi++) {
        int rbase = m0 + wm * 32 + mi * 16;
        float rs0 = rsc[rbase + r0];
        float rs1 = rsc[rbase + r0 + 8];
        #pragma unroll
        for (int nt = 0; nt < 8; nt++) {
            int col = n0 + wn * 64 + nt * 8 + cp;
            float bx = bias ? bias[col] : 0.0f;
            float by = bias ? bias[col + 1] : 0.0f;
            float v00 = fmaf(acc[mi][nt][0], rs0, bx), v01 = fmaf(acc[mi][nt][1], rs0, by);
            float v10 = fmaf(acc[mi][nt][2], rs1, bx), v11 = fmaf(acc[mi][nt][3], rs1, by);
            long long i0 = coff + (long long)(rbase + r0) * Nn + col;
            long long i1 = coff + (long long)(rbase + r0 + 8) * Nn + col;
            uint32_t h0 = pack2bf(v00, v01);
            uint32_t h1 = pack2bf(v10, v11);
            *(uint32_t*)&Ch[i0] = h0;
            *(uint32_t*)&Ch[i1] = h1;
            *(uint32_t*)&Cl[i0] = pack2bf(v00 - bf_lo(h0), v01 - bf_hi(h0));
            *(uint32_t*)&Cl[i1] = pack2bf(v10 - bf_lo(h1), v11 - bf_hi(h1));
        }
    }
}

// ================= flash-style mma attention (128 q-rows / CTA) =============
#define AT_Q_BYTES (2 * 128 * SRA * 2)           // 20480
#define AT_KV_BYTES (4 * 64 * SRA * 2)           // 20480
#define AT_SMEM (AT_Q_BYTES + 2 * AT_KV_BYTES)   // 61440

__global__ __launch_bounds__(256, 2) void attn_mma(
    const __nv_bfloat16* __restrict__ Qh, const __nv_bfloat16* __restrict__ Ql,
    const __nv_bfloat16* __restrict__ Kh, const __nv_bfloat16* __restrict__ Kl,
    const __nv_bfloat16* __restrict__ Vh, const __nv_bfloat16* __restrict__ Vl,
    const uint32_t* __restrict__ maskw,
    __nv_bfloat16* __restrict__ Oh, __nv_bfloat16* __restrict__ Ol)
{
    extern __shared__ char dsm[];
    __nv_bfloat16* sQ = (__nv_bfloat16*)dsm;
    __nv_bfloat16* sK = (__nv_bfloat16*)(dsm + AT_Q_BYTES);
    __nv_bfloat16* sV = (__nv_bfloat16*)(dsm + AT_Q_BYTES + AT_KV_BYTES);
    const uint32_t sQ_u = smem_u32(sQ), sK_u = smem_u32(sK), sV_u = smem_u32(sV);

    const int b = blockIdx.z, h = blockIdx.y, q0 = blockIdx.x * 128;
    const int tid = threadIdx.x, warp = tid >> 5, lane = tid & 31;
    const int rr = lane >> 2, cc = lane & 3;
    const long long bbase = (long long)b * NN * ND + h * HDIM;
    const float KT = 1.4426950408889634f / 5.656854249492381f;

    auto issue_kv = [&](int st, int kc) {
        #pragma unroll
        for (int p = 0; p < 2; p++) {
            const __nv_bfloat16* gk = p ? Kl : Kh;
            const __nv_bfloat16* gv = p ? Vl : Vh;
            int row = tid >> 2, oct = tid & 3;
            uint32_t so = ((st * 2 + p) * 64 * SRA + row * SRA + oct * 8) * 2;
            const long long go = bbase + (long long)(kc + row) * ND + oct * 8;
            cp16(sK_u + so, gk + go);
            cp16(sV_u + so, gv + go);
        }
    };

    // load Q: 2 planes x 128 rows x 4 octs = 1024 cp16 over 256 threads
    #pragma unroll
    for (int p = 0; p < 2; p++) {
        const __nv_bfloat16* gq = p ? Ql : Qh;
        #pragma unroll
        for (int j = 0; j < 2; j++) {
            int lin = tid + j * 256;
            int row = lin >> 2, oct = lin & 3;
            uint32_t so = (p * 128 * SRA + row * SRA + oct * 8) * 2;
            cp16(sQ_u + so, gq + bbase + (long long)(q0 + row) * ND + oct * 8);
        }
    }
    issue_kv(0, 0);
    CP_COMMIT();

    const int qrow0 = q0 + warp * 16 + rr;
    const int qrow1 = qrow0 + 8;

    float mr0 = -60.0f, mr1 = -60.0f;
    float l0 = 0.0f, l1 = 0.0f;
    float oac[4][4];
    #pragma unroll
    for (int i = 0; i < 4; i++)
        #pragma unroll
        for (int j = 0; j < 4; j++) oac[i][j] = 0.0f;

    for (int ct = 0; ct < NN / 64; ct++) {
        if (ct + 1 < NN / 64) issue_kv((ct + 1) & 1, (ct + 1) * 64);
        CP_COMMIT();
        CP_WAIT1();
        __syncthreads();
        const int st = ct & 1;
        const int kc = ct * 64;
        const __nv_bfloat16* kh = sK + (st * 2 + 0) * 64 * SRA;
        const __nv_bfloat16* kl = sK + (st * 2 + 1) * 64 * SRA;
        const __nv_bfloat16* vh = sV + (st * 2 + 0) * 64 * SRA;
        const __nv_bfloat16* vl = sV + (st * 2 + 1) * 64 * SRA;

        float sac[8][4];
        #pragma unroll
        for (int i = 0; i < 8; i++)
            #pragma unroll
            for (int j = 0; j < 4; j++) sac[i][j] = 0.0f;

        #pragma unroll
        for (int ks = 0; ks < 2; ks++) {
            uint32_t qh4[4], ql4[4];
            ldsm_x4(qh4, smem_u32(sQ + (warp * 16 + (lane & 15)) * SRA
                                     + ks * 16 + (lane >> 4) * 8));
            ldsm_x4(ql4, smem_u32(sQ + 128 * SRA + (warp * 16 + (lane & 15)) * SRA
                                     + ks * 16 + (lane >> 4) * 8));
            #pragma unroll
            for (int nj = 0; nj < 4; nj++) {
                uint32_t kh4[4], kl4[4];
                ldsm_x4(kh4, smem_u32(kh + (nj * 16 + (lane & 15)) * SRA
                                         + ks * 16 + (lane >> 4) * 8));
                ldsm_x4(kl4, smem_u32(kl + (nj * 16 + (lane & 15)) * SRA
                                         + ks * 16 + (lane >> 4) * 8));
                mma16816(sac[nj * 2 + 0], qh4, kh4[0], kh4[2]);
                mma16816(sac[nj * 2 + 1], qh4, kh4[1], kh4[3]);
                mma16816(sac[nj * 2 + 0], qh4, kl4[0], kl4[2]);
                mma16816(sac[nj * 2 + 1], qh4, kl4[1], kl4[3]);
                mma16816(sac[nj * 2 + 0], ql4, kh4[0], kh4[2]);
                mma16816(sac[nj * 2 + 1], ql4, kh4[1], kh4[3]);
            }
        }

        uint32_t w00 = maskw[qrow0 * 16 + (kc >> 5)] >> (cc * 2);
        uint32_t w01 = maskw[qrow0 * 16 + (kc >> 5) + 1] >> (cc * 2);
        uint32_t w10 = maskw[qrow1 * 16 + (kc >> 5)] >> (cc * 2);
        uint32_t w11 = maskw[qrow1 * 16 + (kc >> 5) + 1] >> (cc * 2);

        float mx0 = -1e30f, mx1 = -1e30f;
        #pragma unroll
        for (int nt = 0; nt < 8; nt++) {
            mx0 = fmaxf(mx0, fmaxf(sac[nt][0], sac[nt][1]));
            mx1 = fmaxf(mx1, fmaxf(sac[nt][2], sac[nt][3]));
        }
        mx0 *= KT; mx1 *= KT;
        mx0 = fmaxf(mx0, __shfl_xor_sync(0xffffffffu, mx0, 1));
        mx0 = fmaxf(mx0, __shfl_xor_sync(0xffffffffu, mx0, 2));
        mx1 = fmaxf(mx1, __shfl_xor_sync(0xffffffffu, mx1, 1));
        mx1 = fmaxf(mx1, __shfl_xor_sync(0xffffffffu, mx1, 2));
        float mn0 = fmaxf(mr0, mx0), mn1 = fmaxf(mr1, mx1);
        float a0 = exp2_fast(mr0 - mn0), a1 = exp2_fast(mr1 - mn1);
        mr0 = mn0; mr1 = mn1;
        l0 *= a0; l1 *= a1;
        #pragma unroll
        for (int nt = 0; nt < 4; nt++) {
            oac[nt][0] *= a0; oac[nt][1] *= a0;
            oac[nt][2] *= a1; oac[nt][3] *= a1;
        }

        uint32_t ph0[8], ph1[8], pl0[8], pl1[8];
        #pragma unroll
        for (int nt = 0; nt < 8; nt++) {
            uint32_t ws0 = (nt < 4) ? w00 : w01;
            uint32_t ws1 = (nt < 4) ? w10 : w11;
            int sh = (nt & 3) * 8;
            float e00 = exp2_fast(fmaf(sac[nt][0], KT, -mn0));
            float e01 = exp2_fast(fmaf(sac[nt][1], KT, -mn0));
            float e10 = exp2_fast(fmaf(sac[nt][2], KT, -mn1));
            float e11 = exp2_fast(fmaf(sac[nt][3], KT, -mn1));
            e00 = ((ws0 >> (sh + 0)) & 1) ? e00 : 0.0f;
            e01 = ((ws0 >> (sh + 1)) & 1) ? e01 : 0.0f;
            e10 = ((ws1 >> (sh + 0)) & 1) ? e10 : 0.0f;
            e11 = ((ws1 >> (sh + 1)) & 1) ? e11 : 0.0f;
            l0 += e00 + e01;
            l1 += e10 + e11;
            ph0[nt] = pack2bf(e00, e01);
            ph1[nt] = pack2bf(e10, e11);
            pl0[nt] = pack2bf(e00 - bf_lo(ph0[nt]), e01 - bf_hi(ph0[nt]));
            pl1[nt] = pack2bf(e10 - bf_lo(ph1[nt]), e11 - bf_hi(ph1[nt]));
        }

        #pragma unroll
        for (int kb = 0; kb < 4; kb++) {
            uint32_t vha[4], vhb[4], vla[4], vlb[4];
            ldsm_x4_t(vha, smem_u32(vh + (kb * 16 + (lane & 15)) * SRA + (lane >> 4) * 8));
            ldsm_x4_t(vhb, smem_u32(vh + (kb * 16 + (lane & 15)) * SRA + 16 + (lane >> 4) * 8));
            ldsm_x4_t(vla, smem_u32(vl + (kb * 16 + (lane & 15)) * SRA + (lane >> 4) * 8));
            ldsm_x4_t(vlb, smem_u32(vl + (kb * 16 + (lane & 15)) * SRA + 16 + (lane >> 4) * 8));
            uint32_t pah[4] = {ph0[2 * kb], ph1[2 * kb], ph0[2 * kb + 1], ph1[2 * kb + 1]};
            uint32_t pal[4] = {pl0[2 * kb], pl1[2 * kb], pl0[2 * kb + 1], pl1[2 * kb + 1]};
            mma16816(oac[0], pah, vha[0], vha[1]);
            mma16816(oac[1], pah, vha[2], vha[3]);
            mma16816(oac[2], pah, vhb[0], vhb[1]);
            mma16816(oac[3], pah, vhb[2], vhb[3]);
            mma16816(oac[0], pah, vla[0], vla[1]);
            mma16816(oac[1], pah, vla[2], vla[3]);
            mma16816(oac[2], pah, vlb[0], vlb[1]);
            mma16816(oac[3], pah, vlb[2], vlb[3]);
            mma16816(oac[0], pal, vha[0], vha[1]);
            mma16816(oac[1], pal, vha[2], vha[3]);
            mma16816(oac[2], pal, vhb[0], vhb[1]);
            mma16816(oac[3], pal, vhb[2], vhb[3]);
        }
        __syncthreads();
    }

    l0 += __shfl_xor_sync(0xffffffffu, l0, 1);
    l0 += __shfl_xor_sync(0xffffffffu, l0, 2);
    l1 += __shfl_xor_sync(0xffffffffu, l1, 1);
    l1 += __shfl_xor_sync(0xffffffffu, l1, 2);
    float i0 = 1.0f / l0, i1 = 1.0f / l1;

    #pragma unroll
    for (int nt = 0; nt < 4; nt++) {
        int col = h * HDIM + nt * 8 + cc * 2;
        long long idx0 = (long long)(b * NN + qrow0) * ND + col;
        long long idx1 = (long long)(b * NN + qrow1) * ND + col;
        float v00 = oac[nt][0] * i0, v01 = oac[nt][1] * i0;
        float v10 = oac[nt][2] * i1, v11 = oac[nt][3] * i1;
        uint32_t h0 = pack2bf(v00, v01);
        uint32_t h1 = pack2bf(v10, v11);
        *(uint32_t*)&Oh[idx0] = h0;
        *(uint32_t*)&Oh[idx1] = h1;
        *(uint32_t*)&Ol[idx0] = pack2bf(v00 - bf_lo(h0), v01 - bf_hi(h0));
        *(uint32_t*)&Ol[idx1] = pack2bf(v10 - bf_lo(h1), v11 - bf_hi(h1));
    }
}

// ---------------- launch ----------------------------------------------------
extern "C" void kernel_launch(void* const* d_in, const int* in_sizes, int n_in,
                              void* d_out, int out_size) {
    const float* query = (const float*)d_in[0];
    const float* key   = (const float*)d_in[1];
    const float* value = (const float*)d_in[2];
    const int*   edgew = (const int*)d_in[3];
    const int*   mask  = (const int*)d_in[4];
    const float* Wq = (const float*)d_in[5];
    const float* bq = (const float*)d_in[6];
    const float* Wk = (const float*)d_in[7];
    const float* bk = (const float*)d_in[8];
    const float* Wv = (const float*)d_in[9];
    const float* bv = (const float*)d_in[10];
    const float* Wo = (const float*)d_in[11];
    const float* bo = (const float*)d_in[12];

    const int E = in_sizes[3] / 2;

    float *pDI;
    __nv_bfloat16 *pINh, *pINl, *pWh, *pWl, *pAh, *pXWh, *pXWl,
                  *pQVh, *pQVl, *pATh, *pATl;
    uint32_t* pMW;
    cudaGetSymbolAddress((void**)&pDI,  g_dinv);
    cudaGetSymbolAddress((void**)&pINh, g_INh);
    cudaGetSymbolAddress((void**)&pINl, g_INl);
    cudaGetSymbolAddress((void**)&pWh,  g_Wh);
    cudaGetSymbolAddress((void**)&pWl,  g_Wl);
    cudaGetSymbolAddress((void**)&pAh,  g_Ah);
    cudaGetSymbolAddress((void**)&pXWh, g_XWh);
    cudaGetSymbolAddress((void**)&pXWl, g_XWl);
    cudaGetSymbolAddress((void**)&pQVh, g_QVh);
    cudaGetSymbolAddress((void**)&pQVl, g_QVl);
    cudaGetSymbolAddress((void**)&pATh, g_ATh);
    cudaGetSymbolAddress((void**)&pATl, g_ATl);
    cudaGetSymbolAddress((void**)&pMW,  g_maskw);

    // gemm3<2>: stage = (2*5120 + 2*32*72) elem = 14848 -> 29696 B x3
    const int G3_SMEM64 = 3 * (2 * GA_TILE + 2 * KC * 72) * 2;
    cudaFuncSetAttribute(gemm3<2>, cudaFuncAttributeMaxDynamicSharedMemorySize, G3_SMEM64);
    cudaFuncSetAttribute(gemm2, cudaFuncAttributeMaxDynamicSharedMemorySize, G2_SMEM);
    cudaFuncSetAttribute(attn_mma, cudaFuncAttributeMaxDynamicSharedMemorySize, AT_SMEM);

    BiasPtrs nob = {nullptr, nullptr, nullptr};
    BiasPtrs qkvb = {bq, bk, bv};
    BiasPtrs outb = {bo, nullptr, nullptr};

    // preprocessing chain
    k_initmask<<<(NN * NN + 255) / 256, 256>>>(mask, edgew, E);
    k_deg<<<(E + 255) / 256, 256>>>(edgew, E);
    k_dinv<<<(NN + 255) / 256, 256>>>();
    k_buildA<<<(E + NN + 255) / 256, 256>>>(edgew, E);
    k_convertA<<<(NN * NN / 2 + 255) / 256, 256>>>();
    k_split3<<<dim3((BND / 2 + 255) / 256, 3), 256>>>(query, key, value, pINh, pINl, BND / 2);
    k_split4<<<dim3((ND * ND / 2 + 255) / 256, 4), 256>>>(Wq, Wk, Wv, Wo, pWh, pWl, ND * ND / 2);

    // Y = (Dinv X) @ W  (3 tensors merged; N-tile 64 for wave balance)
    gemm3<2><<<dim3(ND / 64, (NB * NN) / 128, 3), 256, G3_SMEM64>>>(
        pINh, pINl, (long long)BND, 0,
        pWh, pWl, (long long)ND * ND, 0,
        nob, nullptr, pXWh, pXWl, (long long)BND, 0,
        ND, ND, 0);

    // QKV = Dinv * (M @ Y) + b   (2-pass exact-integer M)
    gemm2<<<dim3(ND / 128, NN / 128, 3 * NB), 256, G2_SMEM>>>(
        pAh,
        pXWh, pXWl, (long long)BND, (long long)NN * ND,
        qkvb, pDI, pQVh, pQVl, (long long)BND, (long long)NN * ND,
        ND, NN, 5);

    // attention (128 q rows / CTA)
    attn_mma<<<dim3(NN / 128, NH, NB), 256, AT_SMEM>>>(
        pQVh, pQVl,
        pQVh + (long long)BND, pQVl + (long long)BND,
        pQVh + 2LL * BND, pQVl + 2LL * BND,
        pMW, pATh, pATl);

    // out = AT @ Wo + bo  (N-tile 64)
    gemm3<2><<<dim3(ND / 64, (NB * NN) / 128, 1), 256, G3_SMEM64>>>(
        pATh, pATl, 0, 0,
        pWh + 3 * ND * ND, pWl + 3 * ND * ND, 0, 0,
        outb, (float*)d_out, nullptr, nullptr, 0, 0,
        ND, ND, 0);
}